// round 13
// baseline (speedup 1.0000x reference)
#include <cuda_runtime.h>

#define B_   8
#define H_   1024
#define W_   1024
#define NW_  32                      // 32-bit words per column (H/32)
#define NWG  34                      // NW_ + 2 guard word-rows (always zero)
#define NPIX (B_ * H_ * W_)
#define RAD  7                       // truncation radius; rel err ~1.9e-4 << 1e-3

#define LOSS_BLOCKS (B_ * H_ / 4)    // 2048: one block per 4 rows

// Persistent scratch. Guard word-rows 0 and 33 per batch are NEVER written
// -> stay zero from module load. Counters return to ZERO at the end of every
// launch (last loss block resets them).
__device__ unsigned int g_bits[B_ * NWG * W_];
__device__ unsigned int g_spos;
__device__ unsigned int g_done;
__device__ double       g_acc;

// ---------------------------------------------------------------------------
// 1) pack targets>0.5 into per-column bitmasks + count foreground pixels.
// ---------------------------------------------------------------------------
__global__ void __launch_bounds__(256) bg_pack_kernel(const float* __restrict__ targets) {
    int tid = blockIdx.x * blockDim.x + threadIdx.x;   // 0 .. 131071
    int j2  = (tid & 511) * 2;
    int wr  = (tid >> 9) & 31;
    int b   = tid >> 14;

    const float* base = targets + ((size_t)(b * H_ + wr * 32)) * W_ + j2;
    unsigned b0 = 0, b1 = 0;
#pragma unroll 8
    for (int k = 0; k < 32; ++k) {
        float2 v = *(const float2*)(base + (size_t)k * W_);
        unsigned m = 1u << k;
        if (v.x > 0.5f) b0 |= m;
        if (v.y > 0.5f) b1 |= m;
    }
    *(uint2*)(g_bits + (size_t)(b * NWG + wr + 1) * W_ + j2) = make_uint2(b0, b1);

    int c = __popc(b0) + __popc(b1);
#pragma unroll
    for (int off = 16; off; off >>= 1)
        c += __shfl_down_sync(0xffffffffu, c, off);

    __shared__ int ssum[8];
    if ((threadIdx.x & 31) == 0) ssum[threadIdx.x >> 5] = c;
    __syncthreads();
    if (threadIdx.x < 8) {
        int v = ssum[threadIdx.x];
#pragma unroll
        for (int off = 4; off; off >>= 1)
            v += __shfl_down_sync(0xffu, v, off);
        if (threadIdx.x == 0) atomicAdd(&g_spos, (unsigned int)v);
    }
}

// ---------------------------------------------------------------------------
// vertical truncated distance for 4 columns x 4 rows at global column gcol;
// writes packed u16x2 g^2 for row pairs (0,1)->sdA, (2,3)->sdB at local col
// lcol. rb points at word-row wi-1 (guard-safe).
// ---------------------------------------------------------------------------
__device__ __forceinline__ void vert4(const unsigned int* __restrict__ rb, int gcol,
                                      int k, unsigned int* sdA, unsigned int* sdB,
                                      int lcol) {
    uint4 w0v = *(const uint4*)(rb + gcol);              // word row wi-1
    uint4 w1v = *(const uint4*)(rb + W_ + gcol);         // word row wi
    uint4 w2v = *(const uint4*)(rb + 2 * W_ + gcol);     // word row wi+1
    unsigned int w0a[4] = {w0v.x, w0v.y, w0v.z, w0v.w};
    unsigned int w1a[4] = {w1v.x, w1v.y, w1v.z, w1v.w};
    unsigned int w2a[4] = {w2v.x, w2v.y, w2v.z, w2v.w};

    uint4 stA, stB;
    unsigned int* stAp = (unsigned int*)&stA;
    unsigned int* stBp = (unsigned int*)&stB;
#pragma unroll
    for (int c = 0; c < 4; ++c) {
        int g2[4];
#pragma unroll
        for (int r = 0; r < 4; ++r) {
            unsigned int u = __funnelshift_r(w0a[c], w1a[c], k + r);
            unsigned int v = __funnelshift_r(w1a[c], w2a[c], k + r);
            unsigned int C = (u >> 1) | __brev(v);       // bit(31-d)=fg at dist d
            int g = min(__clz(C), RAD);                  // clz(0)=32 -> capped
            g2[r] = g * g;                               // <= 49
        }
        stAp[c] = (unsigned int)g2[0] | ((unsigned int)g2[1] << 16);
        stBp[c] = (unsigned int)g2[2] | ((unsigned int)g2[3] << 16);
    }
    *(uint4*)(sdA + lcol) = stA;
    *(uint4*)(sdB + lcol) = stB;
}

// ---------------------------------------------------------------------------
// horizontal truncated min-plus (|o| <= 7) over a streamed 5-uint4 window,
// then LUT-weighted loss for 2 rows x 4 cols, added to acc (log2 units).
// ---------------------------------------------------------------------------
__device__ __forceinline__ void taps_and_loss(const unsigned int* sd, int lj,
                                              const float* lut,
                                              float4 pAv, float4 pBv, float& acc) {
    unsigned int bestp[4] = {0x7fff7fffu, 0x7fff7fffu, 0x7fff7fffu, 0x7fff7fffu};
    const uint4* wp = (const uint4*)(sd + lj - 8);   // 16B aligned
#pragma unroll
    for (int q = 0; q < 5; ++q) {
        uint4 v = wp[q];
        unsigned int wv[4] = {v.x, v.y, v.z, v.w};
#pragma unroll
        for (int r = 0; r < 4; ++r) {
            const int m = 4 * q + r;                 // window index 0..19
#pragma unroll
            for (int c = 0; c < 4; ++c) {
                const int o = m - 8 - c;             // tap offset
                if (o >= -RAD && o <= RAD) {
                    const unsigned int cc = (unsigned int)(o * o) * 0x00010001u;
                    bestp[c] = __viaddmin_u16x2(wv[r], cc, bestp[c]);
                }
            }
        }
    }
    float pa[4] = {pAv.x, pAv.y, pAv.z, pAv.w};
    float pb[4] = {pBv.x, pBv.y, pBv.z, pBv.w};
#pragma unroll
    for (int c = 0; c < 4; ++c) {
        const unsigned int b2 = bestp[c];
        const int dA = (int)(b2 & 0xffffu);
        const int dB = (int)(b2 >> 16);
        float wA = lut[dA];
        float wB = lut[dB];
        float argA = (dA == 0) ? pa[c] : (1.0f - pa[c]);
        float argB = (dB == 0) ? pb[c] : (1.0f - pb[c]);
        acc += wA * __log2f(argA);
        acc += wB * __log2f(argB);
    }
}

// ---------------------------------------------------------------------------
// 2) loss kernel. One block = 4 adjacent rows, 256 threads = 8 AUTONOMOUS
//    warps. Warp w owns columns 128w..128w+127 for all 4 rows, staging g^2
//    (u16x2 row pairs) in its PRIVATE shared segment with ±8-col halo
//    computed redundantly by lanes 0,1,30,31 -> only __syncwarp() between
//    store and window loads, no mid-kernel block barrier. Per-warp 50-entry
//    weight LUT (wtab[0] = w_pos). Single __syncthreads at final reduction.
// ---------------------------------------------------------------------------
__global__ void __launch_bounds__(256) bg_loss_kernel(const float* __restrict__ probs,
                                                      float* __restrict__ out) {
    __shared__ __align__(16) unsigned int s_seg[8][2][144];  // [warp][pair][8+128+8]
    __shared__ float s_lut[8][64];
    __shared__ float s_red[8];

    const int t    = threadIdx.x;
    const int w    = t >> 5;
    const int lane = t & 31;
    const int bi   = blockIdx.x;          // 0 .. 2047
    const int b    = bi >> 8;
    const int i    = (bi & 255) << 2;     // rows i .. i+3
    const int wi   = i >> 5;
    const int k    = i & 31;              // multiple of 4, <= 28
    const int cb   = w << 7;              // warp column base
    const int lj   = lane << 2;           // local column base 0..124

    unsigned int* sdA = &s_seg[w][0][8];
    unsigned int* sdB = &s_seg[w][1][8];
    float*        lut = s_lut[w];

    // per-warp weight LUT: lut[d2]=min(baseN+exp(-d2/8),1); lut[0]=w_pos
    {
        const float Sp = (float)g_spos;
        const float Sn = (float)NPIX - Sp;
        float w_pos = fminf((Sn + 1e-6f) / (Sp + 1e-6f), 1.0f);
        float baseN = (Sp + 1e-6f) / (Sn + 1e-6f);
        float v = fminf(baseN + __expf((float)lane * -0.125f), 1.0f);
        lut[lane] = (lane == 0) ? w_pos : v;
        int u2 = lane + 32;
        if (u2 < 50)
            lut[u2] = fminf(baseN + __expf((float)u2 * -0.125f), 1.0f);
    }

    const unsigned int* rb = g_bits + (size_t)(b * NWG + wi) * W_;

    // halo columns (local -8..-1 and 128..135), computed or padded at edges
    if (lane < 2 || lane >= 30) {
        int lh = (lane < 2) ? (4 * lane - 8) : (128 + 4 * (lane - 30));
        int gh = cb + lh;
        if (gh < 0 || gh >= W_) {
            uint4 pad = make_uint4(0x00310031u, 0x00310031u, 0x00310031u, 0x00310031u);
            *(uint4*)(sdA + lh) = pad;
            *(uint4*)(sdB + lh) = pad;
        } else {
            vert4(rb, gh, k, sdA, sdB, lh);
        }
    }
    // own 4 columns
    vert4(rb, cb + lj, k, sdA, sdB, lj);

    // prefetch probs rows i, i+1 (in flight across syncwarp + taps)
    const float* pr = probs + ((size_t)(b * H_) + i) * W_ + cb;
    float4 p0 = *(const float4*)(pr + lj);
    float4 p1 = *(const float4*)(pr + W_ + lj);

    __syncwarp();                          // warp-local STS -> LDS ordering

    float acc = 0.0f;
    taps_and_loss(sdA, lj, lut, p0, p1, acc);          // rows i, i+1
    {
        float4 p2 = *(const float4*)(pr + 2 * W_ + lj);
        float4 p3 = *(const float4*)(pr + 3 * W_ + lj);
        taps_and_loss(sdB, lj, lut, p2, p3, acc);      // rows i+2, i+3
    }
    acc *= -0.6931471805599453f;           // log2 -> ln

    // --- block reduction (only block-wide barrier) -> one double atomic ---
#pragma unroll
    for (int off = 16; off; off >>= 1)
        acc += __shfl_down_sync(0xffffffffu, acc, off);
    if (lane == 0) s_red[w] = acc;
    __syncthreads();
    if (t < 8) {
        float v = s_red[t];
#pragma unroll
        for (int off = 4; off; off >>= 1)
            v += __shfl_down_sync(0xffu, v, off);
        if (t == 0) {
            atomicAdd(&g_acc, (double)v);
            __threadfence();
            unsigned int old = atomicAdd(&g_done, 1u);
            if (old == LOSS_BLOCKS - 1) {      // last block finalizes + resets
                double total = *(volatile double*)&g_acc;
                out[0] = (float)(total * (1.0 / (double)NPIX));
                g_acc  = 0.0;
                g_done = 0u;
                g_spos = 0u;
            }
        }
    }
}

extern "C" void kernel_launch(void* const* d_in, const int* in_sizes, int n_in,
                              void* d_out, int out_size) {
    const float* probs   = (const float*)d_in[0];
    const float* targets = (const float*)d_in[1];
    float*       out     = (float*)d_out;

    bg_pack_kernel<<<(B_ * NW_ * W_ / 2) / 256, 256>>>(targets);
    bg_loss_kernel<<<LOSS_BLOCKS, 256>>>(probs, out);
}

// round 14
// speedup vs baseline: 1.2283x; 1.2283x over previous
#include <cuda_runtime.h>

#define B_   8
#define H_   1024
#define W_   1024
#define NW_  32                      // 32-bit words per column (H/32)
#define NWG  34                      // NW_ + 2 guard word-rows (always zero)
#define NPIX (B_ * H_ * W_)
#define RAD  7                       // truncation radius; rel err ~1.9e-4 << 1e-3

#define LOSS_BLOCKS (B_ * H_ / 8)    // 1024: one block per 8 rows (single wave)

// Persistent scratch. Guard word-rows 0 and 33 per batch are NEVER written
// -> stay zero from module load. Counters return to ZERO at the end of every
// launch (last loss block resets them).
__device__ unsigned int g_bits[B_ * NWG * W_];
__device__ unsigned int g_spos;
__device__ unsigned int g_done;
__device__ double       g_acc;

// ---------------------------------------------------------------------------
// 1) pack targets>0.5 into per-column bitmasks + count foreground pixels.
// ---------------------------------------------------------------------------
__global__ void __launch_bounds__(256) bg_pack_kernel(const float* __restrict__ targets) {
    int tid = blockIdx.x * blockDim.x + threadIdx.x;   // 0 .. 131071
    int j2  = (tid & 511) * 2;
    int wr  = (tid >> 9) & 31;
    int b   = tid >> 14;

    const float* base = targets + ((size_t)(b * H_ + wr * 32)) * W_ + j2;
    unsigned b0 = 0, b1 = 0;
#pragma unroll 8
    for (int k = 0; k < 32; ++k) {
        float2 v = *(const float2*)(base + (size_t)k * W_);
        unsigned m = 1u << k;
        if (v.x > 0.5f) b0 |= m;
        if (v.y > 0.5f) b1 |= m;
    }
    *(uint2*)(g_bits + (size_t)(b * NWG + wr + 1) * W_ + j2) = make_uint2(b0, b1);

    int c = __popc(b0) + __popc(b1);
#pragma unroll
    for (int off = 16; off; off >>= 1)
        c += __shfl_down_sync(0xffffffffu, c, off);

    __shared__ int ssum[8];
    if ((threadIdx.x & 31) == 0) ssum[threadIdx.x >> 5] = c;
    __syncthreads();
    if (threadIdx.x < 8) {
        int v = ssum[threadIdx.x];
#pragma unroll
        for (int off = 4; off; off >>= 1)
            v += __shfl_down_sync(0xffu, v, off);
        if (threadIdx.x == 0) atomicAdd(&g_spos, (unsigned int)v);
    }
}

// ---------------------------------------------------------------------------
// horizontal truncated min-plus (|o| <= 7) over a streamed 5-uint4 window,
// then LUT-weighted loss for 2 rows x 4 cols, added to acc (log2 units).
// ---------------------------------------------------------------------------
__device__ __forceinline__ void taps_and_loss(const unsigned int* sd, int lj,
                                              const float* lut,
                                              float4 pAv, float4 pBv, float& acc) {
    unsigned int bestp[4] = {0x7fff7fffu, 0x7fff7fffu, 0x7fff7fffu, 0x7fff7fffu};
    const uint4* wp = (const uint4*)(sd + lj - 8);   // 16B aligned
#pragma unroll
    for (int q = 0; q < 5; ++q) {
        uint4 v = wp[q];
        unsigned int wv[4] = {v.x, v.y, v.z, v.w};
#pragma unroll
        for (int r = 0; r < 4; ++r) {
            const int m = 4 * q + r;                 // window index 0..19
#pragma unroll
            for (int c = 0; c < 4; ++c) {
                const int o = m - 8 - c;             // tap offset
                if (o >= -RAD && o <= RAD) {
                    const unsigned int cc = (unsigned int)(o * o) * 0x00010001u;
                    bestp[c] = __viaddmin_u16x2(wv[r], cc, bestp[c]);
                }
            }
        }
    }
    float pa[4] = {pAv.x, pAv.y, pAv.z, pAv.w};
    float pb[4] = {pBv.x, pBv.y, pBv.z, pBv.w};
#pragma unroll
    for (int c = 0; c < 4; ++c) {
        const unsigned int b2 = bestp[c];
        const int dA = (int)(b2 & 0xffffu);
        const int dB = (int)(b2 >> 16);
        float wA = lut[dA];
        float wB = lut[dB];
        float argA = (dA == 0) ? pa[c] : (1.0f - pa[c]);
        float argB = (dB == 0) ? pb[c] : (1.0f - pb[c]);
        acc += wA * __log2f(argA);
        acc += wB * __log2f(argB);
    }
}

// ---------------------------------------------------------------------------
// 2) loss kernel. One block = 8 adjacent rows (k = i&31 multiple of 8, so ONE
//    set of 3 bit-word LDG.128s covers all vertical windows). Thread t owns
//    columns 4t..4t+3 for all 8 rows. g^2 (u16x2) for the 4 row pairs staged
//    in 4 shared buffers; ONE block barrier, then 4 tap/loss phases with
//    progressively loaded probs. 50-entry weight LUT (wtab[0] = w_pos).
//    Grid 1024 = single wave. Last block finalizes + resets counters.
// ---------------------------------------------------------------------------
__global__ void __launch_bounds__(256) bg_loss_kernel(const float* __restrict__ probs,
                                                      float* __restrict__ out) {
    __shared__ __align__(16) unsigned int s_p[4][8 + W_ + 8];
    __shared__ float s_wtab[50];
    __shared__ float s_red[8];

    const int t  = threadIdx.x;
    const int bi = blockIdx.x;            // 0 .. 1023
    const int b  = bi >> 7;
    const int i  = (bi & 127) << 3;       // rows i .. i+7
    const int wi = i >> 5;
    const int k  = i & 31;                // multiple of 8, <= 24 -> k+7 <= 31
    const int j0 = t * 4;

    if (t < 8) {                          // pads: 49 per lane (never wins)
#pragma unroll
        for (int p = 0; p < 4; ++p) {
            s_p[p][t]           = 0x00310031u;
            s_p[p][8 + W_ + t]  = 0x00310031u;
        }
    }
    if (t < 50) {                         // wtab[d2]=min(baseN+exp(-d2/8),1); wtab[0]=w_pos
        const float Sp = (float)g_spos;
        const float Sn = (float)NPIX - Sp;
        float w_pos = fminf((Sn + 1e-6f) / (Sp + 1e-6f), 1.0f);
        float baseN = (Sp + 1e-6f) / (Sn + 1e-6f);
        float v = fminf(baseN + __expf((float)t * -0.125f), 1.0f);
        s_wtab[t] = (t == 0) ? w_pos : v;
    }

    // --- vertical truncated distance: 4 columns x 8 rows, ONE bit-word set ---
    {
        const unsigned int* rb = g_bits + (size_t)(b * NWG + wi) * W_;
        uint4 w0v = *(const uint4*)(rb + j0);              // word row wi-1 (guarded)
        uint4 w1v = *(const uint4*)(rb + W_ + j0);         // word row wi
        uint4 w2v = *(const uint4*)(rb + 2 * W_ + j0);     // word row wi+1
        unsigned int w0a[4] = {w0v.x, w0v.y, w0v.z, w0v.w};
        unsigned int w1a[4] = {w1v.x, w1v.y, w1v.z, w1v.w};
        unsigned int w2a[4] = {w2v.x, w2v.y, w2v.z, w2v.w};

        uint4 st[4];
#pragma unroll
        for (int c = 0; c < 4; ++c) {
            int g2[8];
#pragma unroll
            for (int r = 0; r < 8; ++r) {
                unsigned int u = __funnelshift_r(w0a[c], w1a[c], k + r);
                unsigned int v = __funnelshift_r(w1a[c], w2a[c], k + r);
                unsigned int C = (u >> 1) | __brev(v);     // bit(31-d)=fg at dist d
                int g = min(__clz(C), RAD);                // clz(0)=32 -> capped
                g2[r] = g * g;                             // <= 49
            }
            ((unsigned int*)&st[0])[c] = (unsigned int)g2[0] | ((unsigned int)g2[1] << 16);
            ((unsigned int*)&st[1])[c] = (unsigned int)g2[2] | ((unsigned int)g2[3] << 16);
            ((unsigned int*)&st[2])[c] = (unsigned int)g2[4] | ((unsigned int)g2[5] << 16);
            ((unsigned int*)&st[3])[c] = (unsigned int)g2[6] | ((unsigned int)g2[7] << 16);
        }
#pragma unroll
        for (int p = 0; p < 4; ++p)
            *(uint4*)(&s_p[p][8] + j0) = st[p];
    }

    // prefetch probs rows i, i+1 (in flight across the barrier)
    const float* pr = probs + ((size_t)(b * H_) + i) * W_;
    float4 p0 = *(const float4*)(pr + j0);
    float4 p1 = *(const float4*)(pr + W_ + j0);

    __syncthreads();                       // the ONLY mid-kernel block barrier

    float acc = 0.0f;
    taps_and_loss(&s_p[0][8], j0, s_wtab, p0, p1, acc);        // rows i, i+1
    {
        float4 p2 = *(const float4*)(pr + 2 * W_ + j0);
        float4 p3 = *(const float4*)(pr + 3 * W_ + j0);
        taps_and_loss(&s_p[1][8], j0, s_wtab, p2, p3, acc);    // rows i+2, i+3
    }
    {
        float4 p4 = *(const float4*)(pr + 4 * W_ + j0);
        float4 p5 = *(const float4*)(pr + 5 * W_ + j0);
        taps_and_loss(&s_p[2][8], j0, s_wtab, p4, p5, acc);    // rows i+4, i+5
    }
    {
        float4 p6 = *(const float4*)(pr + 6 * W_ + j0);
        float4 p7 = *(const float4*)(pr + 7 * W_ + j0);
        taps_and_loss(&s_p[3][8], j0, s_wtab, p6, p7, acc);    // rows i+6, i+7
    }
    acc *= -0.6931471805599453f;           // log2 -> ln

    // --- block reduction -> one double atomic per block ---
#pragma unroll
    for (int off = 16; off; off >>= 1)
        acc += __shfl_down_sync(0xffffffffu, acc, off);
    if ((t & 31) == 0) s_red[t >> 5] = acc;
    __syncthreads();
    if (t < 8) {
        float v = s_red[t];
#pragma unroll
        for (int off = 4; off; off >>= 1)
            v += __shfl_down_sync(0xffu, v, off);
        if (t == 0) {
            atomicAdd(&g_acc, (double)v);
            __threadfence();
            unsigned int old = atomicAdd(&g_done, 1u);
            if (old == LOSS_BLOCKS - 1) {      // last block finalizes + resets
                double total = *(volatile double*)&g_acc;
                out[0] = (float)(total * (1.0 / (double)NPIX));
                g_acc  = 0.0;
                g_done = 0u;
                g_spos = 0u;
            }
        }
    }
}

extern "C" void kernel_launch(void* const* d_in, const int* in_sizes, int n_in,
                              void* d_out, int out_size) {
    const float* probs   = (const float*)d_in[0];
    const float* targets = (const float*)d_in[1];
    float*       out     = (float*)d_out;

    bg_pack_kernel<<<(B_ * NW_ * W_ / 2) / 256, 256>>>(targets);
    bg_loss_kernel<<<LOSS_BLOCKS, 256>>>(probs, out);
}